// round 6
// baseline (speedup 1.0000x reference)
#include <cuda_runtime.h>

// NonMaximaSuppression2d: out = x * (x > max over 3x3 neighborhood excluding
// center), replicate padding. (8,4,2048,2048) fp32. HBM-bound stream.
//
// R6 = R5 (best: 158.4us) + ROWS=8 in two front-batched 4-row chunks:
// 10 row-loads per 8 output rows (1.25x/row vs 1.5x), same 6-row register
// window (shift 2 rows between chunks), interior no-clamp fast path, __stcs.

#define TPB 128          // 128 threads * float4 = 512 px per block in x
#define RPT 8            // output rows per thread (two 4-row chunks)

__device__ __forceinline__ float max3(float a, float b, float c) {
    return fmaxf(fmaxf(a, b), c);
}

// Compute+store 4 output rows from a 6-row window (v/lh/rh), rows start at ybase.
__device__ __forceinline__ void
compute4(const float4 v[6], const float lh[6], const float rh[6],
         float* __restrict__ q, int W, int x4, int ybase) {
    #pragma unroll
    for (int r = 0; r < 4; r++) {
        const int t = r, m = r + 1, b = r + 2;

        float t0 = max3(lh[t], v[t].x, v[t].y);
        float t1 = max3(v[t].x, v[t].y, v[t].z);
        float t2 = max3(v[t].y, v[t].z, v[t].w);
        float t3 = max3(v[t].z, v[t].w, rh[t]);

        float b0 = max3(lh[b], v[b].x, v[b].y);
        float b1 = max3(v[b].x, v[b].y, v[b].z);
        float b2 = max3(v[b].y, v[b].z, v[b].w);
        float b3 = max3(v[b].z, v[b].w, rh[b]);

        float n0 = fmaxf(lh[m],  v[m].y);
        float n1 = fmaxf(v[m].x, v[m].z);
        float n2 = fmaxf(v[m].y, v[m].w);
        float n3 = fmaxf(v[m].z, rh[m]);

        float4 o;
        float nb;
        nb = fmaxf(fmaxf(t0, b0), n0); o.x = (v[m].x > nb) ? v[m].x : 0.0f;
        nb = fmaxf(fmaxf(t1, b1), n1); o.y = (v[m].y > nb) ? v[m].y : 0.0f;
        nb = fmaxf(fmaxf(t2, b2), n2); o.z = (v[m].z > nb) ? v[m].z : 0.0f;
        nb = fmaxf(fmaxf(t3, b3), n3); o.w = (v[m].w > nb) ? v[m].w : 0.0f;

        __stcs(reinterpret_cast<float4*>(q + (size_t)(ybase + r) * W + x4), o);
    }
}

// Load one padded row (image row yy, clamped if CLAMP) + halos via shuffle.
template <bool CLAMP>
__device__ __forceinline__ void
load_row(const float* __restrict__ p, int H, int W, int x4, int yy, int lane,
         float4& v, float& lh, float& rh) {
    const int y = CLAMP ? min(max(yy, 0), H - 1) : yy;
    const float* row = p + (size_t)y * W;
    v = *reinterpret_cast<const float4*>(row + x4);
    float fl = __shfl_up_sync(0xffffffffu, v.w, 1);
    float fr = __shfl_down_sync(0xffffffffu, v.x, 1);
    if (lane == 0)  fl = (x4 > 0)     ? __ldg(row + x4 - 1) : v.x;  // replicate x
    if (lane == 31) fr = (x4 + 4 < W) ? __ldg(row + x4 + 4) : v.w;  // replicate x
    lh = fl; rh = fr;
}

template <bool CLAMP>
__device__ __forceinline__ void
nms_tile(const float* __restrict__ p, float* __restrict__ q,
         int H, int W, int x4, int y0, int lane) {
    float4 v[6];
    float lh[6], rh[6];

    // ---- Chunk A: rows y0-1 .. y0+4 (6 independent loads, high MLP) ----
    #pragma unroll
    for (int j = 0; j < 6; j++)
        load_row<CLAMP>(p, H, W, x4, y0 + j - 1, lane, v[j], lh[j], rh[j]);
    compute4(v, lh, rh, q, W, x4, y0);

    // ---- Shift window down 4 rows: keep rows y0+3, y0+4 ----
    v[0] = v[4];  lh[0] = lh[4];  rh[0] = rh[4];
    v[1] = v[5];  lh[1] = lh[5];  rh[1] = rh[5];

    // ---- Chunk B: rows y0+5 .. y0+8 (4 independent loads) ----
    #pragma unroll
    for (int j = 2; j < 6; j++)
        load_row<CLAMP>(p, H, W, x4, y0 + j + 3, lane, v[j], lh[j], rh[j]);
    compute4(v, lh, rh, q, W, x4, y0 + 4);
}

__global__ void __launch_bounds__(TPB)
nms2d_kernel(const float* __restrict__ x, float* __restrict__ out,
             int H, int W) {
    const int img = blockIdx.z;
    const size_t base = (size_t)img * H * W;
    const float* __restrict__ p = x + base;
    float* __restrict__ q = out + base;

    const int lane = threadIdx.x & 31;
    const int x4 = (blockIdx.x * TPB + threadIdx.x) * 4;
    const int y0 = blockIdx.y * RPT;

    if (y0 > 0 && y0 + RPT < H) {
        nms_tile<false>(p, q, H, W, x4, y0, lane);   // interior: no y clamps
    } else {
        nms_tile<true>(p, q, H, W, x4, y0, lane);    // top/bottom edge strips
    }
}

extern "C" void kernel_launch(void* const* d_in, const int* in_sizes, int n_in,
                              void* d_out, int out_size) {
    const float* x = (const float*)d_in[0];
    float* out = (float*)d_out;

    const int H = 2048, W = 2048;
    const int n_img = in_sizes[0] / (H * W);   // 32

    dim3 block(TPB, 1, 1);
    dim3 grid(W / (TPB * 4), H / RPT, n_img);
    nms2d_kernel<<<grid, block>>>(x, out, H, W);
}

// round 7
// speedup vs baseline: 1.3267x; 1.3267x over previous
#include <cuda_runtime.h>

// NonMaximaSuppression2d: out = x * (x > max over 3x3 neighborhood excluding
// center), replicate padding. (8,4,2048,2048) fp32. HBM-bound stream.
//
// R7 = R6's traffic shape (8 rows/thread, 10 row-loads per 8 outputs) with
// R5's scheduling: ALL loads of a chunk issued back-to-back (MLP=6 / MLP=4)
// BEFORE any shuffle consumes them. R6 fused LDG+SHFL per row, which made
// every shuffle wait on its own load and collapsed MLP -> 208us.

#define TPB 128          // 128 threads * float4 = 512 px per block in x
#define RPT 8            // output rows per thread (two 4-row chunks)

__device__ __forceinline__ float max3(float a, float b, float c) {
    return fmaxf(fmaxf(a, b), c);
}

// Halo extraction for one loaded row (shuffles + predicated edge loads).
template <bool CLAMP>
__device__ __forceinline__ void
halo_row(const float* __restrict__ p, int H, int W, int x4, int yy, int lane,
         const float4& v, float& lh, float& rh) {
    float fl = __shfl_up_sync(0xffffffffu, v.w, 1);
    float fr = __shfl_down_sync(0xffffffffu, v.x, 1);
    if (lane == 0 || lane == 31) {
        const int y = CLAMP ? min(max(yy, 0), H - 1) : yy;
        const float* row = p + (size_t)y * W;
        if (lane == 0)  fl = (x4 > 0)     ? __ldg(row + x4 - 1) : v.x;
        if (lane == 31) fr = (x4 + 4 < W) ? __ldg(row + x4 + 4) : v.w;
    }
    lh = fl; rh = fr;
}

// Compute+store 4 output rows from a 6-row window, outputs start at ybase.
__device__ __forceinline__ void
compute4(const float4 v[6], const float lh[6], const float rh[6],
         float* __restrict__ q, int W, int x4, int ybase) {
    #pragma unroll
    for (int r = 0; r < 4; r++) {
        const int t = r, m = r + 1, b = r + 2;

        float t0 = max3(lh[t], v[t].x, v[t].y);
        float t1 = max3(v[t].x, v[t].y, v[t].z);
        float t2 = max3(v[t].y, v[t].z, v[t].w);
        float t3 = max3(v[t].z, v[t].w, rh[t]);

        float b0 = max3(lh[b], v[b].x, v[b].y);
        float b1 = max3(v[b].x, v[b].y, v[b].z);
        float b2 = max3(v[b].y, v[b].z, v[b].w);
        float b3 = max3(v[b].z, v[b].w, rh[b]);

        float n0 = fmaxf(lh[m],  v[m].y);
        float n1 = fmaxf(v[m].x, v[m].z);
        float n2 = fmaxf(v[m].y, v[m].w);
        float n3 = fmaxf(v[m].z, rh[m]);

        float4 o;
        float nb;
        nb = fmaxf(fmaxf(t0, b0), n0); o.x = (v[m].x > nb) ? v[m].x : 0.0f;
        nb = fmaxf(fmaxf(t1, b1), n1); o.y = (v[m].y > nb) ? v[m].y : 0.0f;
        nb = fmaxf(fmaxf(t2, b2), n2); o.z = (v[m].z > nb) ? v[m].z : 0.0f;
        nb = fmaxf(fmaxf(t3, b3), n3); o.w = (v[m].w > nb) ? v[m].w : 0.0f;

        __stcs(reinterpret_cast<float4*>(q + (size_t)(ybase + r) * W + x4), o);
    }
}

template <bool CLAMP>
__device__ __forceinline__ float4
load4(const float* __restrict__ p, int H, int W, int x4, int yy) {
    const int y = CLAMP ? min(max(yy, 0), H - 1) : yy;
    return *reinterpret_cast<const float4*>(p + (size_t)y * W + x4);
}

template <bool CLAMP>
__device__ __forceinline__ void
nms_tile(const float* __restrict__ p, float* __restrict__ q,
         int H, int W, int x4, int y0, int lane) {
    float4 v[6];
    float lh[6], rh[6];

    // ---- Chunk A: batch-load rows y0-1 .. y0+4 (6 independent LDG.128) ----
    #pragma unroll
    for (int j = 0; j < 6; j++)
        v[j] = load4<CLAMP>(p, H, W, x4, y0 + j - 1);
    // Halos (shuffles only touch already-requested data)
    #pragma unroll
    for (int j = 0; j < 6; j++)
        halo_row<CLAMP>(p, H, W, x4, y0 + j - 1, lane, v[j], lh[j], rh[j]);
    compute4(v, lh, rh, q, W, x4, y0);

    // ---- Shift window down 4: keep rows y0+3, y0+4 ----
    v[0] = v[4];  lh[0] = lh[4];  rh[0] = rh[4];
    v[1] = v[5];  lh[1] = lh[5];  rh[1] = rh[5];

    // ---- Chunk B: batch-load rows y0+5 .. y0+8 (4 independent LDG.128) ----
    #pragma unroll
    for (int j = 2; j < 6; j++)
        v[j] = load4<CLAMP>(p, H, W, x4, y0 + j + 3);
    #pragma unroll
    for (int j = 2; j < 6; j++)
        halo_row<CLAMP>(p, H, W, x4, y0 + j + 3, lane, v[j], lh[j], rh[j]);
    compute4(v, lh, rh, q, W, x4, y0 + 4);
}

__global__ void __launch_bounds__(TPB)
nms2d_kernel(const float* __restrict__ x, float* __restrict__ out,
             int H, int W) {
    const int img = blockIdx.z;
    const size_t base = (size_t)img * H * W;
    const float* __restrict__ p = x + base;
    float* __restrict__ q = out + base;

    const int lane = threadIdx.x & 31;
    const int x4 = (blockIdx.x * TPB + threadIdx.x) * 4;
    const int y0 = blockIdx.y * RPT;

    if (y0 > 0 && y0 + RPT < H) {
        nms_tile<false>(p, q, H, W, x4, y0, lane);   // interior: no y clamps
    } else {
        nms_tile<true>(p, q, H, W, x4, y0, lane);    // top/bottom edge strips
    }
}

extern "C" void kernel_launch(void* const* d_in, const int* in_sizes, int n_in,
                              void* d_out, int out_size) {
    const float* x = (const float*)d_in[0];
    float* out = (float*)d_out;

    const int H = 2048, W = 2048;
    const int n_img = in_sizes[0] / (H * W);   // 32

    dim3 block(TPB, 1, 1);
    dim3 grid(W / (TPB * 4), H / RPT, n_img);
    nms2d_kernel<<<grid, block>>>(x, out, H, W);
}

// round 8
// speedup vs baseline: 1.3318x; 1.0039x over previous
#include <cuda_runtime.h>

// NonMaximaSuppression2d: out = x * (x > max over 3x3 neighborhood excluding
// center), replicate padding. (8,4,2048,2048) fp32. HBM-bound stream.
//
// R8 = R7 (best: 156.7us) + compile-time H=W=2048: all row offsets become
// LDG/STG [R+imm] immediates (row stride = 1<<11 floats), killing the
// runtime IMAD-wide address chains that made alu=40% of issue.

#define TPB 128          // 128 threads * float4 = 512 px per block in x
#define RPT 8            // output rows per thread (two 4-row chunks)
#define HH  2048
#define WW  2048

__device__ __forceinline__ float max3(float a, float b, float c) {
    return fmaxf(fmaxf(a, b), c);
}

// Halo extraction for one loaded row (shuffles + predicated edge loads).
template <bool CLAMP>
__device__ __forceinline__ void
halo_row(const float* __restrict__ p, int x4, int yy, int lane,
         const float4& v, float& lh, float& rh) {
    float fl = __shfl_up_sync(0xffffffffu, v.w, 1);
    float fr = __shfl_down_sync(0xffffffffu, v.x, 1);
    if (lane == 0 || lane == 31) {
        const int y = CLAMP ? min(max(yy, 0), HH - 1) : yy;
        const float* row = p + ((size_t)y << 11);
        if (lane == 0)  fl = (x4 > 0)      ? __ldg(row + x4 - 1) : v.x;
        if (lane == 31) fr = (x4 + 4 < WW) ? __ldg(row + x4 + 4) : v.w;
    }
    lh = fl; rh = fr;
}

// Compute+store 4 output rows from a 6-row window; qb = &out[ybase][x4].
__device__ __forceinline__ void
compute4(const float4 v[6], const float lh[6], const float rh[6],
         float* __restrict__ qb) {
    #pragma unroll
    for (int r = 0; r < 4; r++) {
        const int t = r, m = r + 1, b = r + 2;

        float t0 = max3(lh[t], v[t].x, v[t].y);
        float t1 = max3(v[t].x, v[t].y, v[t].z);
        float t2 = max3(v[t].y, v[t].z, v[t].w);
        float t3 = max3(v[t].z, v[t].w, rh[t]);

        float b0 = max3(lh[b], v[b].x, v[b].y);
        float b1 = max3(v[b].x, v[b].y, v[b].z);
        float b2 = max3(v[b].y, v[b].z, v[b].w);
        float b3 = max3(v[b].z, v[b].w, rh[b]);

        float n0 = fmaxf(lh[m],  v[m].y);
        float n1 = fmaxf(v[m].x, v[m].z);
        float n2 = fmaxf(v[m].y, v[m].w);
        float n3 = fmaxf(v[m].z, rh[m]);

        float4 o;
        float nb;
        nb = fmaxf(fmaxf(t0, b0), n0); o.x = (v[m].x > nb) ? v[m].x : 0.0f;
        nb = fmaxf(fmaxf(t1, b1), n1); o.y = (v[m].y > nb) ? v[m].y : 0.0f;
        nb = fmaxf(fmaxf(t2, b2), n2); o.z = (v[m].z > nb) ? v[m].z : 0.0f;
        nb = fmaxf(fmaxf(t3, b3), n3); o.w = (v[m].w > nb) ? v[m].w : 0.0f;

        __stcs(reinterpret_cast<float4*>(qb + r * WW), o);   // STG [R+imm]
    }
}

template <bool CLAMP>
__device__ __forceinline__ float4
load4(const float* __restrict__ p, int x4, int yy) {
    const int y = CLAMP ? min(max(yy, 0), HH - 1) : yy;
    return *reinterpret_cast<const float4*>(p + ((size_t)y << 11) + x4);
}

template <bool CLAMP>
__device__ __forceinline__ void
nms_tile(const float* __restrict__ p, float* __restrict__ q,
         int x4, int y0, int lane) {
    float4 v[6];
    float lh[6], rh[6];

    // ---- Chunk A: batch-load rows y0-1 .. y0+4 (6 independent LDG.128) ----
    #pragma unroll
    for (int j = 0; j < 6; j++)
        v[j] = load4<CLAMP>(p, x4, y0 + j - 1);
    #pragma unroll
    for (int j = 0; j < 6; j++)
        halo_row<CLAMP>(p, x4, y0 + j - 1, lane, v[j], lh[j], rh[j]);
    float* qb = q + ((size_t)y0 << 11) + x4;
    compute4(v, lh, rh, qb);

    // ---- Shift window down 4: keep rows y0+3, y0+4 ----
    v[0] = v[4];  lh[0] = lh[4];  rh[0] = rh[4];
    v[1] = v[5];  lh[1] = lh[5];  rh[1] = rh[5];

    // ---- Chunk B: batch-load rows y0+5 .. y0+8 (4 independent LDG.128) ----
    #pragma unroll
    for (int j = 2; j < 6; j++)
        v[j] = load4<CLAMP>(p, x4, y0 + j + 3);
    #pragma unroll
    for (int j = 2; j < 6; j++)
        halo_row<CLAMP>(p, x4, y0 + j + 3, lane, v[j], lh[j], rh[j]);
    compute4(v, lh, rh, qb + 4 * WW);
}

__global__ void __launch_bounds__(TPB)
nms2d_kernel(const float* __restrict__ x, float* __restrict__ out) {
    const int img = blockIdx.z;
    const size_t base = (size_t)img * HH * WW;
    const float* __restrict__ p = x + base;
    float* __restrict__ q = out + base;

    const int lane = threadIdx.x & 31;
    const int x4 = (blockIdx.x * TPB + threadIdx.x) * 4;
    const int y0 = blockIdx.y * RPT;

    if (y0 > 0 && y0 + RPT < HH) {
        nms_tile<false>(p, q, x4, y0, lane);   // interior: no y clamps
    } else {
        nms_tile<true>(p, q, x4, y0, lane);    // top/bottom edge strips
    }
}

extern "C" void kernel_launch(void* const* d_in, const int* in_sizes, int n_in,
                              void* d_out, int out_size) {
    const float* x = (const float*)d_in[0];
    float* out = (float*)d_out;

    const int n_img = in_sizes[0] / (HH * WW);   // 32

    dim3 block(TPB, 1, 1);
    dim3 grid(WW / (TPB * 4), HH / RPT, n_img);
    nms2d_kernel<<<grid, block>>>(x, out);
}